// round 8
// baseline (speedup 1.0000x reference)
#include <cuda_runtime.h>
#include <cuda_bf16.h>
#include <cstdint>

#define BB 64
#define II 128
#define AA 16
#define HH 1024
#define BH (BB*HH)

// scratch (static __device__ — no allocations)
__device__ float g_so[BH];              // sign_j * output[b,j]
__device__ float g_ff[BH];              // b_h + relu(x)@|W_x|^T + relu(aux)@|W_aux|^T
__device__ unsigned int g_gq[HH*HH];    // packed bf16: lo = 0.02*|W_h|, hi = |kappa|

// ---------------- prep: pack (0.02*|W_h|, |kappa|) as bf16x2 (vectorized) ----------------
__global__ void prep_gq(const float4* __restrict__ Wh, const float4* __restrict__ kap) {
    int idx = blockIdx.x * blockDim.x + threadIdx.x;    // over HH*HH/4
    if (idx >= HH * HH / 4) return;
    float4 wv = Wh[idx];
    float4 kv = kap[idx];
    uint4 o;
    o.x = (unsigned)__bfloat16_as_ushort(__float2bfloat16_rn(0.02f * fabsf(wv.x)))
        | ((unsigned)__bfloat16_as_ushort(__float2bfloat16_rn(fabsf(kv.x))) << 16);
    o.y = (unsigned)__bfloat16_as_ushort(__float2bfloat16_rn(0.02f * fabsf(wv.y)))
        | ((unsigned)__bfloat16_as_ushort(__float2bfloat16_rn(fabsf(kv.y))) << 16);
    o.z = (unsigned)__bfloat16_as_ushort(__float2bfloat16_rn(0.02f * fabsf(wv.z)))
        | ((unsigned)__bfloat16_as_ushort(__float2bfloat16_rn(fabsf(kv.z))) << 16);
    o.w = (unsigned)__bfloat16_as_ushort(__float2bfloat16_rn(0.02f * fabsf(wv.w)))
        | ((unsigned)__bfloat16_as_ushort(__float2bfloat16_rn(fabsf(kv.w))) << 16);
    ((uint4*)g_gq)[idx] = o;
}

// ---------------- prep: signed output + feedforward drive (warp per output) ----------------
__global__ __launch_bounds__(256) void prep_soff(const float* __restrict__ x,
                                                 const float* __restrict__ outp,
                                                 const float* __restrict__ aux,
                                                 const float* __restrict__ Wx,
                                                 const float* __restrict__ Waux,
                                                 const float* __restrict__ bh,
                                                 const float* __restrict__ mask) {
    const int warp = threadIdx.x >> 5;
    const int lane = threadIdx.x & 31;
    const int row = blockIdx.x * 8 + warp;        // (b,i)
    const int b = row >> 10;
    const int i = row & (HH - 1);

    float4 w = ((const float4*)(Wx + i * II))[lane];
    float4 xv = ((const float4*)(x + b * II))[lane];
    float acc = fmaxf(xv.x, 0.f) * fabsf(w.x) + fmaxf(xv.y, 0.f) * fabsf(w.y)
              + fmaxf(xv.z, 0.f) * fabsf(w.z) + fmaxf(xv.w, 0.f) * fabsf(w.w);
    if (lane < 4) {
        float4 wa = ((const float4*)(Waux + i * AA))[lane];
        float4 av = ((const float4*)(aux + b * AA))[lane];
        acc += fmaxf(av.x, 0.f) * fabsf(wa.x) + fmaxf(av.y, 0.f) * fabsf(wa.y)
             + fmaxf(av.z, 0.f) * fabsf(wa.z) + fmaxf(av.w, 0.f) * fabsf(wa.w);
    }
#pragma unroll
    for (int off = 16; off; off >>= 1) acc += __shfl_down_sync(0xffffffffu, acc, off);
    if (lane == 0) {
        g_ff[row] = acc + bh[i];
        // mask_h[r, j] = sign_j for any r != j (zero diagonal) -> read row (i+1)%H
        float sgn = mask[((i + 1) & (HH - 1)) * HH + i];
        g_so[row] = sgn * outp[row];
    }
}

// ---------------- pass 1: 8 rows per block -> 8 LDG.128 in flight per thread ----------------
__global__ __launch_bounds__(256) void k_state8(const float* __restrict__ wh,
                                                const float* __restrict__ state,
                                                float* __restrict__ out_state,
                                                float* __restrict__ out_output) {
    __shared__ float red[8 * 8];
    const int row0 = blockIdx.x * 8;              // 8 consecutive rows, same batch (8 | 1024)
    const int b = row0 >> 10;
    const int t = threadIdx.x;                    // 256 threads x 4 cols

    // front-batched independent loads: 8 wh rows + shared so vector
    const float4* wp = (const float4*)(wh + (size_t)row0 * HH) + t;
    float4 w0 = wp[0];
    float4 w1 = wp[256];
    float4 w2 = wp[512];
    float4 w3 = wp[768];
    float4 w4 = wp[1024];
    float4 w5 = wp[1280];
    float4 w6 = wp[1536];
    float4 w7 = wp[1792];
    float4 s  = *(const float4*)(g_so + (b << 10) + 4 * t);

    float a[8];
    a[0] = w0.x * s.x + w0.y * s.y + w0.z * s.z + w0.w * s.w;
    a[1] = w1.x * s.x + w1.y * s.y + w1.z * s.z + w1.w * s.w;
    a[2] = w2.x * s.x + w2.y * s.y + w2.z * s.z + w2.w * s.w;
    a[3] = w3.x * s.x + w3.y * s.y + w3.z * s.z + w3.w * s.w;
    a[4] = w4.x * s.x + w4.y * s.y + w4.z * s.z + w4.w * s.w;
    a[5] = w5.x * s.x + w5.y * s.y + w5.z * s.z + w5.w * s.w;
    a[6] = w6.x * s.x + w6.y * s.y + w6.z * s.z + w6.w * s.w;
    a[7] = w7.x * s.x + w7.y * s.y + w7.z * s.z + w7.w * s.w;

    // zero-diagonal fixups (owner thread of column i subtracts locally)
#pragma unroll
    for (int r = 0; r < 8; r++) {
        int i = (row0 + r) & (HH - 1);
        if (t == (i >> 2)) {
            int c = i & 3;
            float4 w = (r == 0) ? w0 : (r == 1) ? w1 : (r == 2) ? w2 : (r == 3) ? w3
                     : (r == 4) ? w4 : (r == 5) ? w5 : (r == 6) ? w6 : w7;
            float wv = (c == 0) ? w.x : (c == 1) ? w.y : (c == 2) ? w.z : w.w;
            float sv = (c == 0) ? s.x : (c == 1) ? s.y : (c == 2) ? s.z : s.w;
            a[r] -= wv * sv;
        }
    }
#pragma unroll
    for (int off = 16; off; off >>= 1) {
#pragma unroll
        for (int r = 0; r < 8; r++) a[r] += __shfl_down_sync(0xffffffffu, a[r], off);
    }
    if ((t & 31) == 0) {
        int w = t >> 5;
#pragma unroll
        for (int r = 0; r < 8; r++) red[w * 8 + r] = a[r];
    }
    __syncthreads();
    if (t < 8) {
        float total = g_ff[row0 + t];
#pragma unroll
        for (int w = 0; w < 8; w++) total += red[w * 8 + t];
        float ns = 0.8f * state[row0 + t] + 0.2f * total;
        out_state[row0 + t] = ns;
        out_output[row0 + t] = ns > 0.f ? tanhf(ns) : 0.f;   // retanh
    }
}

// ---------------- pass 2: plasticity, 4 rows per block -> 4x read MLP ----------------
__device__ __forceinline__ float4 plast4(float4 w, uint4 gq, float4 no, float coef) {
    float4 r;
    {
        float g = __bfloat162float(__ushort_as_bfloat16((unsigned short)(gq.x & 0xffff)));
        float q = __bfloat162float(__ushort_as_bfloat16((unsigned short)(gq.x >> 16)));
        r.x = fminf(fmaxf(g + 0.98f * w.x + coef * q * no.x, 0.f), 1.f);
    }
    {
        float g = __bfloat162float(__ushort_as_bfloat16((unsigned short)(gq.y & 0xffff)));
        float q = __bfloat162float(__ushort_as_bfloat16((unsigned short)(gq.y >> 16)));
        r.y = fminf(fmaxf(g + 0.98f * w.y + coef * q * no.y, 0.f), 1.f);
    }
    {
        float g = __bfloat162float(__ushort_as_bfloat16((unsigned short)(gq.z & 0xffff)));
        float q = __bfloat162float(__ushort_as_bfloat16((unsigned short)(gq.z >> 16)));
        r.z = fminf(fmaxf(g + 0.98f * w.z + coef * q * no.z, 0.f), 1.f);
    }
    {
        float g = __bfloat162float(__ushort_as_bfloat16((unsigned short)(gq.w & 0xffff)));
        float q = __bfloat162float(__ushort_as_bfloat16((unsigned short)(gq.w >> 16)));
        r.w = fminf(fmaxf(g + 0.98f * w.w + coef * q * no.w, 0.f), 1.f);
    }
    return r;
}

__global__ __launch_bounds__(256) void k_plast4(const float* __restrict__ wh,
                                                const float* __restrict__ da,
                                                const float* __restrict__ newout,
                                                float* __restrict__ out_w) {
    const int row0 = blockIdx.x * 4;              // 4 consecutive rows, same batch (4 | 1024)
    const int b = row0 >> 10;
    const float dab = 0.02f * da[b];

    const int t = threadIdx.x;                    // 256 threads x 4 cols per row
    const size_t base = (size_t)row0 * HH + 4 * t;
    const int i0 = row0 & (HH - 1);

    // front-batch 4 independent wh DRAM reads (MLP=4)
    float4 wA = __ldcs((const float4*)(wh + base));
    float4 wB = __ldcs((const float4*)(wh + base + HH));
    float4 wC = __ldcs((const float4*)(wh + base + 2 * HH));
    float4 wD = __ldcs((const float4*)(wh + base + 3 * HH));
    // gq rows (L2-resident, 4 MB total) + shared newout vector
    const unsigned* gqp = g_gq + i0 * HH + 4 * t;
    uint4 gA = *(const uint4*)(gqp);
    uint4 gB = *(const uint4*)(gqp + HH);
    uint4 gC = *(const uint4*)(gqp + 2 * HH);
    uint4 gD = *(const uint4*)(gqp + 3 * HH);
    float4 no = *(const float4*)(newout + (b << 10) + 4 * t);

    const float* nor = newout + row0;
    float cA = dab * nor[0];
    float cB = dab * nor[1];
    float cC = dab * nor[2];
    float cD = dab * nor[3];

    __stcs((float4*)(out_w + base),          plast4(wA, gA, no, cA));
    __stcs((float4*)(out_w + base + HH),     plast4(wB, gB, no, cB));
    __stcs((float4*)(out_w + base + 2 * HH), plast4(wC, gC, no, cC));
    __stcs((float4*)(out_w + base + 3 * HH), plast4(wD, gD, no, cD));
}

extern "C" void kernel_launch(void* const* d_in, const int* in_sizes, int n_in,
                              void* d_out, int out_size) {
    const float* x      = (const float*)d_in[0];   // [B,I]
    const float* state  = (const float*)d_in[1];   // [B,H]
    const float* outp   = (const float*)d_in[2];   // [B,H]
    const float* wh     = (const float*)d_in[3];   // [B,H,H]
    const float* da     = (const float*)d_in[4];   // [B]
    const float* aux    = (const float*)d_in[5];   // [B,A]
    const float* Wx     = (const float*)d_in[6];   // [H,I]
    const float* Waux   = (const float*)d_in[7];   // [H,A]
    const float* Wh     = (const float*)d_in[8];   // [H,H]
    const float* bh     = (const float*)d_in[9];   // [H]
    const float* kappa  = (const float*)d_in[10];  // [H,H]
    const float* mask   = (const float*)d_in[11];  // [H,H]

    float* out_state  = (float*)d_out;                 // [B,H]
    float* out_output = (float*)d_out + BH;            // [B,H]
    float* out_w      = (float*)d_out + 2 * BH;        // [B,H,H]

    prep_soff<<<BH / 8, 256>>>(x, outp, aux, Wx, Waux, bh, mask);
    prep_gq<<<(HH * HH / 4 + 255) / 256, 256>>>((const float4*)Wh, (const float4*)kappa);
    k_state8<<<BH / 8, 256>>>(wh, state, out_state, out_output);
    k_plast4<<<BH / 4, 256>>>(wh, da, out_output, out_w);
}